// round 13
// baseline (speedup 1.0000x reference)
#include <cuda_runtime.h>
#include <cuda_fp16.h>
#include <math.h>
#include <stdint.h>

#define NB     64
#define SHIFT  150
#define LEN    200
#define NH     128
#define MTILE  64
#define NCHUNK 8
#define EPSF   1e-7f
#define HALF_INV_LN10 0.21714724095162588f

#define FP     200                  // frame pitch (halfs); rows -> banks 4r mod 32
#define BP     56                   // B pitch (halfs); rows -> banks 28r mod 32
#define KC     48                   // K per chunk (3 k16 steps); 48*4 + 16 = 208
#define NCHK   5
#define BCH    28672                // bytes per split chunk: 256*56*2

// per-CTA smem layout (bytes)
#define SM_FH   0                   // frames hi [64][200] half = 25600
#define SM_FL   25600
#define SM_BH   51200               // B chunk hi [256][56] half
#define SM_BL   79872
#define SMEM_TOTAL 108544

// epilogue overlay (over frames region; pitch 68 floats)
#define OFF_V    0                  // [128][68] f32 = 34816
#define OFF_MEAN 34816
#define OFF_INV  35328
#define OFF_PS   35840              // partial sums [2][64]
#define OFF_PQ   36352

#define PREPN  (NCHK * 256 * BP)    // 71680 prep elements

__device__ float g_mu[NB];
__device__ float g_sd[NB];
__device__ float g_psum[NB * NCHUNK];
__device__ float g_psq [NB * NCHUNK];
__device__ __align__(16) __half g_bh[PREPN];
__device__ __align__(16) __half g_bl[PREPN];

__device__ __forceinline__ void mma16(float* d, const uint32_t* a, const uint32_t* bf) {
    asm volatile("mma.sync.aligned.m16n8k16.row.col.f32.f16.f16.f32 "
        "{%0,%1,%2,%3}, {%4,%5,%6,%7}, {%8,%9}, {%0,%1,%2,%3};"
        : "+f"(d[0]), "+f"(d[1]), "+f"(d[2]), "+f"(d[3])
        : "r"(a[0]), "r"(a[1]), "r"(a[2]), "r"(a[3]), "r"(bf[0]), "r"(bf[1]));
}
__device__ __forceinline__ void ldsm4(uint32_t* r, uint32_t addr) {
    asm volatile("ldmatrix.sync.aligned.m8n8.x4.shared.b16 {%0,%1,%2,%3}, [%4];"
        : "=r"(r[0]), "=r"(r[1]), "=r"(r[2]), "=r"(r[3]) : "r"(addr));
}
__device__ __forceinline__ void cpa16(uint32_t dst, const void* src) {
    asm volatile("cp.async.cg.shared.global [%0], [%1], 16;" :: "r"(dst), "l"(src));
}
__device__ __forceinline__ void cpa_commit() {
    asm volatile("cp.async.commit_group;" ::: "memory");
}
template <int N>
__device__ __forceinline__ void cpa_wait() {
    asm volatile("cp.async.wait_group %0;" :: "n"(N) : "memory");
}

// ---------------------------------------------------------------------------
__global__ void __launch_bounds__(256)
stats_partial(const float* __restrict__ x, int S) {
    const int b = blockIdx.x, c = blockIdx.y;
    const int chunk = (S + NCHUNK - 1) / NCHUNK;
    const int s0 = c * chunk;
    const int s1 = min(s0 + chunk, S);
    const float* xb = x + (size_t)b * S + s0;
    const int n = s1 - s0;

    float sum = 0.f, sq = 0.f;
    int pre = (int)(((16u - (unsigned)((size_t)xb & 15u)) & 15u) >> 2);
    if (pre > n) pre = n;
    for (int i = threadIdx.x; i < pre; i += 256) { float v = xb[i]; sum += v; sq += v*v; }
    int n4 = (n - pre) >> 2;
    const float4* x4 = (const float4*)(xb + pre);
    for (int i = threadIdx.x; i < n4; i += 256) {
        float4 v = x4[i];
        sum += v.x + v.y + v.z + v.w;
        sq  += v.x*v.x + v.y*v.y + v.z*v.z + v.w*v.w;
    }
    for (int i = pre + (n4 << 2) + threadIdx.x; i < n; i += 256) { float v = xb[i]; sum += v; sq += v*v; }

    __shared__ float ssum[8], ssq[8];
    #pragma unroll
    for (int o = 16; o > 0; o >>= 1) {
        sum += __shfl_xor_sync(~0u, sum, o);
        sq  += __shfl_xor_sync(~0u, sq,  o);
    }
    int w = threadIdx.x >> 5, ln = threadIdx.x & 31;
    if (ln == 0) { ssum[w] = sum; ssq[w] = sq; }
    __syncthreads();
    if (w == 0 && ln < 8) {
        sum = ssum[ln]; sq = ssq[ln];
        #pragma unroll
        for (int o = 4; o > 0; o >>= 1) {
            sum += __shfl_xor_sync(0xffu, sum, o);
            sq  += __shfl_xor_sync(0xffu, sq,  o);
        }
        if (ln == 0) { g_psum[b*NCHUNK+c] = sum; g_psq[b*NCHUNK+c] = sq; }
    }
}

// ---------------------------------------------------------------------------
// Merged: block 0 finalizes mu/sd; blocks 1.. prep the split-fp16 B arrays.
// ---------------------------------------------------------------------------
__global__ void finalize_and_prep(const float* __restrict__ kr,
                                  const float* __restrict__ ki, int S) {
    if (blockIdx.x == 0) {
        int b = threadIdx.x;
        if (b >= NB) return;
        float sum = 0.f, sq = 0.f;
        #pragma unroll
        for (int c = 0; c < NCHUNK; c++) { sum += g_psum[b*NCHUNK+c]; sq += g_psq[b*NCHUNK+c]; }
        float mu  = sum / (float)S;
        float var = sq / (float)S - mu * mu;
        g_mu[b] = mu;
        g_sd[b] = sqrtf(fmaxf(var, 0.f));
        return;
    }
    int idx = (blockIdx.x - 1) * 256 + threadIdx.x;
    if (idx >= PREPN) return;
    int kk = idx % BP;
    int n  = (idx / BP) & 255;
    int c  = idx / (256 * BP);
    int k  = c * KC + kk;
    float v = 0.f;
    if (kk < KC && k < LEN)
        v = ((n < NH) ? kr : ki)[(size_t)(n & 127) * LEN + k];
    __half h = __float2half_rn(v);
    g_bh[idx] = h;
    g_bl[idx] = __float2half_rn(v - __half2float(h));
}

// ---------------------------------------------------------------------------
// Fused: frame+normalize (fp16 hi/lo) + 3xFP16 HMMA DFT
// ldmatrix frags, cp.async B staging, in-warp re/im pairing, div-free staging.
// grid (T/64, NB), 256 threads = 8 warps (2m x 4n); warp tile 32t x 32n(re+im).
// ---------------------------------------------------------------------------
__global__ void __launch_bounds__(256, 2)
dft_mma_kernel(const float* __restrict__ x,
               float* __restrict__ out, int S, int T) {
    extern __shared__ char smem[];
    const uint32_t smb = (uint32_t)__cvta_generic_to_shared(smem);

    const int tid  = threadIdx.x;
    const int lane = tid & 31;
    const int wid  = tid >> 5;
    const int g    = lane >> 2;
    const int q    = lane & 3;
    const int wm   = wid & 1;
    const int wn   = wid >> 1;
    const int tw   = wm * 32;
    const int nw   = wn * 32;

    const int b  = blockIdx.y;
    const int t0 = blockIdx.x * MTILE;
    const float mu  = g_mu[b];
    const float inv = 1.f / (g_sd[b] + EPSF);
    const float* xrow = x + (size_t)b * S + (size_t)t0 * SHIFT;

    // kick off B chunk 0 while frames stage
    for (int i = tid * 16; i < BCH; i += 256 * 16) {
        cpa16(smb + SM_BH + i, (const char*)g_bh + i);
        cpa16(smb + SM_BL + i, (const char*)g_bl + i);
    }
    cpa_commit();

    // stage frames, div-free: thread -> (row tr = tid>>2, quarter c4 = tid&3),
    // each thread converts 25 k-pairs. STS banks (4*tr + 25*c4) mod 32: all distinct.
    {
        const int tr = tid >> 2;
        const int c4 = tid & 3;
        const float* src = xrow + tr * SHIFT + c4 * 50;
        uint32_t* fh = (uint32_t*)(smem + SM_FH) + tr * (FP / 2) + c4 * 25;
        uint32_t* fl = (uint32_t*)(smem + SM_FL) + tr * (FP / 2) + c4 * 25;
        #pragma unroll 5
        for (int j = 0; j < 25; j++) {
            float2 v2 = *(const float2*)(src + 2 * j);
            float v0 = (v2.x - mu) * inv;
            float v1 = (v2.y - mu) * inv;
            __half h0 = __float2half_rn(v0), h1 = __float2half_rn(v1);
            __half l0 = __float2half_rn(v0 - __half2float(h0));
            __half l1 = __float2half_rn(v1 - __half2float(h1));
            fh[j] = (uint32_t)__half_as_ushort(h0) | ((uint32_t)__half_as_ushort(h1) << 16);
            fl[j] = (uint32_t)__half_as_ushort(l0) | ((uint32_t)__half_as_ushort(l1) << 16);
        }
    }

    float acc[2][8][4];
    #pragma unroll
    for (int mt = 0; mt < 2; mt++)
        #pragma unroll
        for (int nt = 0; nt < 8; nt++)
            #pragma unroll
            for (int i = 0; i < 4; i++) acc[mt][nt][i] = 0.f;

    // per-lane ldmatrix bases
    const uint32_t aAh = smb + SM_FH +
        (uint32_t)(((tw + (lane & 15)) * FP + ((lane >> 4) << 3)) * 2);
    const uint32_t aAl = aAh + (SM_FL - SM_FH);
    const uint32_t bOff =
        (uint32_t)((((lane & 7) + ((lane >> 4) << 3)) * BP + ((lane >> 3) & 1) * 8) * 2);
    const uint32_t aBh0 = smb + SM_BH + bOff + (uint32_t)(nw * BP * 2);
    const uint32_t aBl0 = smb + SM_BL + bOff + (uint32_t)(nw * BP * 2);

    for (int c = 0; c < NCHK; c++) {
        cpa_wait<0>();
        __syncthreads();

        const int nsteps = (c < 4) ? 3 : 1;
        #pragma unroll
        for (int ks = 0; ks < 3; ks++) {
            if (ks >= nsteps) break;
            const uint32_t kgb = (uint32_t)((c * KC + ks * 16) * 2);  // A k offset, bytes
            const uint32_t klb = (uint32_t)((ks * 16) * 2);           // B local k offset

            uint32_t ah[2][4], al[2][4];
            ldsm4(ah[0], aAh + kgb);
            ldsm4(ah[1], aAh + kgb + 16 * FP * 2);
            ldsm4(al[0], aAl + kgb);
            ldsm4(al[1], aAl + kgb + 16 * FP * 2);

            #pragma unroll
            for (int h = 0; h < 2; h++) {     // h=0: re rows n, h=1: im rows n+128
                const uint32_t hb = (uint32_t)(h * 128 * BP * 2) + klb;
                uint32_t bh4[2][4], bl4[2][4];
                ldsm4(bh4[0], aBh0 + hb);
                ldsm4(bh4[1], aBh0 + hb + 16 * BP * 2);
                ldsm4(bl4[0], aBl0 + hb);
                ldsm4(bl4[1], aBl0 + hb + 16 * BP * 2);

                uint32_t bhf[4][2], blf[4][2];
                #pragma unroll
                for (int u = 0; u < 4; u++) {
                    bhf[u][0] = bh4[u >> 1][(u & 1) * 2];
                    bhf[u][1] = bh4[u >> 1][(u & 1) * 2 + 1];
                    blf[u][0] = bl4[u >> 1][(u & 1) * 2];
                    blf[u][1] = bl4[u >> 1][(u & 1) * 2 + 1];
                }
                #pragma unroll
                for (int u = 0; u < 4; u++) {
                    mma16(acc[0][h * 4 + u], ah[0], bhf[u]);
                    mma16(acc[1][h * 4 + u], ah[1], bhf[u]);
                }
                #pragma unroll
                for (int u = 0; u < 4; u++) {
                    mma16(acc[0][h * 4 + u], al[0], bhf[u]);
                    mma16(acc[1][h * 4 + u], al[1], bhf[u]);
                }
                #pragma unroll
                for (int u = 0; u < 4; u++) {
                    mma16(acc[0][h * 4 + u], ah[0], blf[u]);
                    mma16(acc[1][h * 4 + u], ah[1], blf[u]);
                }
            }
        }
        __syncthreads();

        // stage next chunk
        if (c < NCHK - 1) {
            const char* sH = (const char*)(g_bh + (c + 1) * 256 * BP);
            const char* sL = (const char*)(g_bl + (c + 1) * 256 * BP);
            for (int i = tid * 16; i < BCH; i += 256 * 16) {
                cpa16(smb + SM_BH + i, sH + i);
                cpa16(smb + SM_BL + i, sL + i);
            }
            cpa_commit();
        }
    }

    // ---- epilogue: thread-local mag/log (re = nt, im = nt+4) ----
    float* vst = (float*)(smem + OFF_V);
    #pragma unroll
    for (int mt = 0; mt < 2; mt++)
        #pragma unroll
        for (int j = 0; j < 4; j++)
            #pragma unroll
            for (int e = 0; e < 4; e++) {
                const int n = nw + j * 8 + 2 * q + (e & 1);
                const int t = tw + mt * 16 + g + ((e >> 1) << 3);
                float re = acc[mt][j][e];
                float im = acc[mt][j + 4][e];
                float m2 = fmaxf(re * re + im * im, 1e-14f);
                vst[n * 68 + t] = __logf(m2) * HALF_INV_LN10;
            }
    __syncthreads();

    float* mn  = (float*)(smem + OFF_MEAN);
    float* ivn = (float*)(smem + OFF_INV);
    float* ps  = (float*)(smem + OFF_PS);
    float* pq  = (float*)(smem + OFF_PQ);
    if (tid < 2 * MTILE) {
        const int t = tid & 63, h = tid >> 6;
        float sum = 0.f, sq = 0.f;
        #pragma unroll 8
        for (int n = h * 64; n < h * 64 + 64; n++) {
            float v = vst[n * 68 + t];
            sum += v; sq += v * v;
        }
        ps[tid] = sum; pq[tid] = sq;
    }
    __syncthreads();
    if (tid < MTILE) {
        const float sum = ps[tid] + ps[tid + 64];
        const float sq  = pq[tid] + pq[tid + 64];
        const float mean = sum * (1.f / NH);
        const float var  = sq * (1.f / NH) - mean * mean;
        mn[tid]  = mean;
        ivn[tid] = 1.f / (sqrtf(fmaxf(var, 0.f)) + EPSF);
    }
    __syncthreads();
    for (int idx = tid; idx < NH * MTILE; idx += 256) {
        const int n = idx >> 6, t = idx & 63;
        out[((size_t)(b * NH + n)) * T + t0 + t] = (vst[n * 68 + t] - mn[t]) * ivn[t];
    }
}

// ---------------------------------------------------------------------------
extern "C" void kernel_launch(void* const* d_in, const int* in_sizes, int n_in,
                              void* d_out, int out_size) {
    const float* x  = (const float*)d_in[0];
    const float* kr = (const float*)d_in[1];
    const float* ki = (const float*)d_in[2];
    float* out = (float*)d_out;

    const int S = in_sizes[0] / NB;            // 480050
    const int T = (S - LEN) / SHIFT + 1;       // 3200

    cudaFuncSetAttribute(dft_mma_kernel, cudaFuncAttributeMaxDynamicSharedMemorySize, SMEM_TOTAL);

    stats_partial<<<dim3(NB, NCHUNK), 256>>>(x, S);
    finalize_and_prep<<<1 + (PREPN + 255) / 256, 256>>>(kr, ki, S);
    dft_mma_kernel<<<dim3(T / MTILE, NB), 256, SMEM_TOTAL>>>(x, out, S, T);
}

// round 14
// speedup vs baseline: 1.1191x; 1.1191x over previous
#include <cuda_runtime.h>
#include <cuda_fp16.h>
#include <math.h>
#include <stdint.h>

#define NB     64
#define SHIFT  150
#define LEN    200
#define NH     128
#define MTILE  64
#define NCHUNK 16
#define EPSF   1e-7f
#define HALF_INV_LN10 0.21714724095162588f

#define FP     200                  // frame pitch (halfs); rows -> banks 4r mod 32
#define BP     56                   // B pitch (halfs); rows -> banks 28r mod 32
#define KC     48                   // K per chunk (3 k16 steps); 48*4 + 16 = 208
#define NCHK   5
#define BCH    28672                // bytes per split chunk: 256*56*2

// per-CTA smem layout (bytes)
#define SM_FH   0                   // frames hi [64][200] half = 25600
#define SM_FL   25600
#define SM_BH   51200               // B chunk hi [256][56] half
#define SM_BL   79872
#define SMEM_TOTAL 108544

// epilogue overlay (over frames region; pitch 68 floats)
#define OFF_V    0                  // [128][68] f32 = 34816
#define OFF_MEAN 34816
#define OFF_INV  35328
#define OFF_PS   35840              // partial sums [2][64]
#define OFF_PQ   36352

#define PREPN  (NCHK * 256 * BP)    // 71680 prep elements

__device__ float g_mu[NB];
__device__ float g_sd[NB];
__device__ float g_psum[NB * NCHUNK];
__device__ float g_psq [NB * NCHUNK];
__device__ __align__(16) __half g_bh[PREPN];
__device__ __align__(16) __half g_bl[PREPN];

__device__ __forceinline__ void mma16(float* d, const uint32_t* a, const uint32_t* bf) {
    asm volatile("mma.sync.aligned.m16n8k16.row.col.f32.f16.f16.f32 "
        "{%0,%1,%2,%3}, {%4,%5,%6,%7}, {%8,%9}, {%0,%1,%2,%3};"
        : "+f"(d[0]), "+f"(d[1]), "+f"(d[2]), "+f"(d[3])
        : "r"(a[0]), "r"(a[1]), "r"(a[2]), "r"(a[3]), "r"(bf[0]), "r"(bf[1]));
}
__device__ __forceinline__ void ldsm4(uint32_t* r, uint32_t addr) {
    asm volatile("ldmatrix.sync.aligned.m8n8.x4.shared.b16 {%0,%1,%2,%3}, [%4];"
        : "=r"(r[0]), "=r"(r[1]), "=r"(r[2]), "=r"(r[3]) : "r"(addr));
}
__device__ __forceinline__ void cpa16(uint32_t dst, const void* src) {
    asm volatile("cp.async.cg.shared.global [%0], [%1], 16;" :: "r"(dst), "l"(src));
}
__device__ __forceinline__ void cpa_commit() {
    asm volatile("cp.async.commit_group;" ::: "memory");
}
template <int N>
__device__ __forceinline__ void cpa_wait() {
    asm volatile("cp.async.wait_group %0;" :: "n"(N) : "memory");
}
__device__ __forceinline__ void group_bar(int id) {
    asm volatile("bar.sync %0, 64;" :: "r"(id) : "memory");
}

// ---------------------------------------------------------------------------
__global__ void __launch_bounds__(256)
stats_partial(const float* __restrict__ x, int S) {
    const int b = blockIdx.x, c = blockIdx.y;
    const int chunk = (S + NCHUNK - 1) / NCHUNK;
    const int s0 = c * chunk;
    const int s1 = min(s0 + chunk, S);
    const float* xb = x + (size_t)b * S + s0;
    const int n = s1 - s0;

    float sum = 0.f, sq = 0.f;
    int pre = (int)(((16u - (unsigned)((size_t)xb & 15u)) & 15u) >> 2);
    if (pre > n) pre = n;
    for (int i = threadIdx.x; i < pre; i += 256) { float v = xb[i]; sum += v; sq += v*v; }
    int n4 = (n - pre) >> 2;
    const float4* x4 = (const float4*)(xb + pre);
    for (int i = threadIdx.x; i < n4; i += 256) {
        float4 v = x4[i];
        sum += v.x + v.y + v.z + v.w;
        sq  += v.x*v.x + v.y*v.y + v.z*v.z + v.w*v.w;
    }
    for (int i = pre + (n4 << 2) + threadIdx.x; i < n; i += 256) { float v = xb[i]; sum += v; sq += v*v; }

    __shared__ float ssum[8], ssq[8];
    #pragma unroll
    for (int o = 16; o > 0; o >>= 1) {
        sum += __shfl_xor_sync(~0u, sum, o);
        sq  += __shfl_xor_sync(~0u, sq,  o);
    }
    int w = threadIdx.x >> 5, ln = threadIdx.x & 31;
    if (ln == 0) { ssum[w] = sum; ssq[w] = sq; }
    __syncthreads();
    if (w == 0 && ln < 8) {
        sum = ssum[ln]; sq = ssq[ln];
        #pragma unroll
        for (int o = 4; o > 0; o >>= 1) {
            sum += __shfl_xor_sync(0xffu, sum, o);
            sq  += __shfl_xor_sync(0xffu, sq,  o);
        }
        if (ln == 0) { g_psum[b*NCHUNK+c] = sum; g_psq[b*NCHUNK+c] = sq; }
    }
}

// ---------------------------------------------------------------------------
// Merged: block 0 finalizes mu/sd; blocks 1.. prep the split-fp16 B arrays.
// ---------------------------------------------------------------------------
__global__ void finalize_and_prep(const float* __restrict__ kr,
                                  const float* __restrict__ ki, int S) {
    if (blockIdx.x == 0) {
        int b = threadIdx.x;
        if (b >= NB) return;
        float sum = 0.f, sq = 0.f;
        #pragma unroll
        for (int c = 0; c < NCHUNK; c++) { sum += g_psum[b*NCHUNK+c]; sq += g_psq[b*NCHUNK+c]; }
        float mu  = sum / (float)S;
        float var = sq / (float)S - mu * mu;
        g_mu[b] = mu;
        g_sd[b] = sqrtf(fmaxf(var, 0.f));
        return;
    }
    int idx = (blockIdx.x - 1) * 256 + threadIdx.x;
    if (idx >= PREPN) return;
    int kk = idx % BP;
    int n  = (idx / BP) & 255;
    int c  = idx / (256 * BP);
    int k  = c * KC + kk;
    float v = 0.f;
    if (kk < KC && k < LEN)
        v = ((n < NH) ? kr : ki)[(size_t)(n & 127) * LEN + k];
    __half h = __float2half_rn(v);
    g_bh[idx] = h;
    g_bl[idx] = __float2half_rn(v - __half2float(h));
}

// ---------------------------------------------------------------------------
// Fused: frame+normalize (fp16 hi/lo) + 3xFP16 HMMA DFT
// Group-private B staging (2-warp named barriers, zero CTA-wide mainloop syncs),
// ldmatrix frags, in-warp re/im pairing.
// grid (T/64, NB), 256 threads = 8 warps (2m x 4n); warp tile 32t x 32n(re+im).
// ---------------------------------------------------------------------------
__global__ void __launch_bounds__(256, 2)
dft_mma_kernel(const float* __restrict__ x,
               float* __restrict__ out, int S, int T) {
    extern __shared__ char smem[];
    const uint32_t smb = (uint32_t)__cvta_generic_to_shared(smem);

    const int tid  = threadIdx.x;
    const int lane = tid & 31;
    const int wid  = tid >> 5;
    const int g    = lane >> 2;
    const int q    = lane & 3;
    const int wm   = wid & 1;
    const int wn   = wid >> 1;
    const int tw   = wm * 32;
    const int nw   = wn * 32;
    const int gtid = tid & 63;          // thread id within 2-warp group
    const int barid = 1 + wn;           // named barrier per group

    const int b  = blockIdx.y;
    const int t0 = blockIdx.x * MTILE;
    const float mu  = g_mu[b];
    const float inv = 1.f / (g_sd[b] + EPSF);
    const float* xrow = x + (size_t)b * S + (size_t)t0 * SHIFT;

    // stage frames, div-free: thread -> (row tr = tid>>2, quarter c4 = tid&3)
    {
        const int tr = tid >> 2;
        const int c4 = tid & 3;
        const float* src = xrow + tr * SHIFT + c4 * 50;
        uint32_t* fh = (uint32_t*)(smem + SM_FH) + tr * (FP / 2) + c4 * 25;
        uint32_t* fl = (uint32_t*)(smem + SM_FL) + tr * (FP / 2) + c4 * 25;
        #pragma unroll 5
        for (int j = 0; j < 25; j++) {
            float2 v2 = *(const float2*)(src + 2 * j);
            float v0 = (v2.x - mu) * inv;
            float v1 = (v2.y - mu) * inv;
            __half h0 = __float2half_rn(v0), h1 = __float2half_rn(v1);
            __half l0 = __float2half_rn(v0 - __half2float(h0));
            __half l1 = __float2half_rn(v1 - __half2float(h1));
            fh[j] = (uint32_t)__half_as_ushort(h0) | ((uint32_t)__half_as_ushort(h1) << 16);
            fl[j] = (uint32_t)__half_as_ushort(l0) | ((uint32_t)__half_as_ushort(l1) << 16);
        }
    }
    __syncthreads();   // A visible to all warps; last CTA-wide sync until epilogue

    float acc[2][8][4];
    #pragma unroll
    for (int mt = 0; mt < 2; mt++)
        #pragma unroll
        for (int nt = 0; nt < 8; nt++)
            #pragma unroll
            for (int i = 0; i < 4; i++) acc[mt][nt][i] = 0.f;

    // per-lane ldmatrix bases
    const uint32_t aAh = smb + SM_FH +
        (uint32_t)(((tw + (lane & 15)) * FP + ((lane >> 4) << 3)) * 2);
    const uint32_t aAl = aAh + (SM_FL - SM_FH);
    const uint32_t bOff =
        (uint32_t)((((lane & 7) + ((lane >> 4) << 3)) * BP + ((lane >> 3) & 1) * 8) * 2);
    const uint32_t aBh0 = smb + SM_BH + bOff + (uint32_t)(nw * BP * 2);
    const uint32_t aBl0 = smb + SM_BL + bOff + (uint32_t)(nw * BP * 2);

    // group-private B staging offsets (rows nw..nw+31 and 128+nw..128+nw+31)
    const int baseRe = nw * 112;                 // byte offset of re slice
    const int baseIm = (128 + nw) * 112 - 3584;  // im slice, rebased

    for (int c = 0; c < NCHK; c++) {
        // stage this group's B rows for chunk c
        {
            const char* srcH = (const char*)g_bh + c * BCH;
            const char* srcL = (const char*)g_bl + c * BCH;
            #pragma unroll
            for (int j = 0; j < 7; j++) {
                const int idx = j * 1024 + gtid * 16;
                const int off = ((idx >= 3584) ? baseIm : baseRe) + idx;
                cpa16(smb + SM_BH + off, srcH + off);
                cpa16(smb + SM_BL + off, srcL + off);
            }
            cpa_commit();
            cpa_wait<0>();
            group_bar(barid);
        }

        const int nsteps = (c < 4) ? 3 : 1;
        #pragma unroll
        for (int ks = 0; ks < 3; ks++) {
            if (ks >= nsteps) break;
            const uint32_t kgb = (uint32_t)((c * KC + ks * 16) * 2);  // A k offset, bytes
            const uint32_t klb = (uint32_t)((ks * 16) * 2);           // B local k offset

            uint32_t ah[2][4], al[2][4];
            ldsm4(ah[0], aAh + kgb);
            ldsm4(ah[1], aAh + kgb + 16 * FP * 2);
            ldsm4(al[0], aAl + kgb);
            ldsm4(al[1], aAl + kgb + 16 * FP * 2);

            #pragma unroll
            for (int h = 0; h < 2; h++) {     // h=0: re rows, h=1: im rows
                const uint32_t hb = (uint32_t)(h * 128 * BP * 2) + klb;
                uint32_t bh4[2][4], bl4[2][4];
                ldsm4(bh4[0], aBh0 + hb);
                ldsm4(bh4[1], aBh0 + hb + 16 * BP * 2);
                ldsm4(bl4[0], aBl0 + hb);
                ldsm4(bl4[1], aBl0 + hb + 16 * BP * 2);

                uint32_t bhf[4][2], blf[4][2];
                #pragma unroll
                for (int u = 0; u < 4; u++) {
                    bhf[u][0] = bh4[u >> 1][(u & 1) * 2];
                    bhf[u][1] = bh4[u >> 1][(u & 1) * 2 + 1];
                    blf[u][0] = bl4[u >> 1][(u & 1) * 2];
                    blf[u][1] = bl4[u >> 1][(u & 1) * 2 + 1];
                }
                #pragma unroll
                for (int u = 0; u < 4; u++) {
                    mma16(acc[0][h * 4 + u], ah[0], bhf[u]);
                    mma16(acc[1][h * 4 + u], ah[1], bhf[u]);
                }
                #pragma unroll
                for (int u = 0; u < 4; u++) {
                    mma16(acc[0][h * 4 + u], al[0], bhf[u]);
                    mma16(acc[1][h * 4 + u], al[1], bhf[u]);
                }
                #pragma unroll
                for (int u = 0; u < 4; u++) {
                    mma16(acc[0][h * 4 + u], ah[0], blf[u]);
                    mma16(acc[1][h * 4 + u], ah[1], blf[u]);
                }
            }
        }
        group_bar(barid);   // both warps done with chunk c before overwrite
    }
    __syncthreads();        // all warps done; frames region now dead

    // ---- epilogue: thread-local mag/log (re = nt, im = nt+4) ----
    float* vst = (float*)(smem + OFF_V);
    #pragma unroll
    for (int mt = 0; mt < 2; mt++)
        #pragma unroll
        for (int j = 0; j < 4; j++)
            #pragma unroll
            for (int e = 0; e < 4; e++) {
                const int n = nw + j * 8 + 2 * q + (e & 1);
                const int t = tw + mt * 16 + g + ((e >> 1) << 3);
                float re = acc[mt][j][e];
                float im = acc[mt][j + 4][e];
                float m2 = fmaxf(re * re + im * im, 1e-14f);
                vst[n * 68 + t] = __logf(m2) * HALF_INV_LN10;
            }
    __syncthreads();

    float* mn  = (float*)(smem + OFF_MEAN);
    float* ivn = (float*)(smem + OFF_INV);
    float* ps  = (float*)(smem + OFF_PS);
    float* pq  = (float*)(smem + OFF_PQ);
    if (tid < 2 * MTILE) {
        const int t = tid & 63, h = tid >> 6;
        float sum = 0.f, sq = 0.f;
        #pragma unroll 8
        for (int n = h * 64; n < h * 64 + 64; n++) {
            float v = vst[n * 68 + t];
            sum += v; sq += v * v;
        }
        ps[tid] = sum; pq[tid] = sq;
    }
    __syncthreads();
    if (tid < MTILE) {
        const float sum = ps[tid] + ps[tid + 64];
        const float sq  = pq[tid] + pq[tid + 64];
        const float mean = sum * (1.f / NH);
        const float var  = sq * (1.f / NH) - mean * mean;
        mn[tid]  = mean;
        ivn[tid] = 1.f / (sqrtf(fmaxf(var, 0.f)) + EPSF);
    }
    __syncthreads();
    for (int idx = tid; idx < NH * MTILE; idx += 256) {
        const int n = idx >> 6, t = idx & 63;
        out[((size_t)(b * NH + n)) * T + t0 + t] = (vst[n * 68 + t] - mn[t]) * ivn[t];
    }
}

// ---------------------------------------------------------------------------
extern "C" void kernel_launch(void* const* d_in, const int* in_sizes, int n_in,
                              void* d_out, int out_size) {
    const float* x  = (const float*)d_in[0];
    const float* kr = (const float*)d_in[1];
    const float* ki = (const float*)d_in[2];
    float* out = (float*)d_out;

    const int S = in_sizes[0] / NB;            // 480050
    const int T = (S - LEN) / SHIFT + 1;       // 3200

    cudaFuncSetAttribute(dft_mma_kernel, cudaFuncAttributeMaxDynamicSharedMemorySize, SMEM_TOTAL);

    stats_partial<<<dim3(NB, NCHUNK), 256>>>(x, S);
    finalize_and_prep<<<1 + (PREPN + 255) / 256, 256>>>(kr, ki, S);
    dft_mma_kernel<<<dim3(T / MTILE, NB), 256, SMEM_TOTAL>>>(x, out, S, T);
}